// round 9
// baseline (speedup 1.0000x reference)
#include <cuda_runtime.h>
#include <cuda_bf16.h>
#include <cstdint>

// Problem constants
constexpr int Nn = 50000;
constexpr int D  = 128;
constexpr int E  = 800000;
constexpr int SCAN_B = 512;
constexpr int SCAN_G = (Nn + SCAN_B - 1) / SCAN_B;   // 98

// Scratch (static device globals)
__device__ float g_aggr[(size_t)Nn * D];   // seeded with x, then += segment sums
__device__ float g_stats[2 * D];
__device__ int   g_cnt[Nn];
__device__ int   g_start[Nn];
__device__ int   g_cur[Nn];
__device__ int   g_bsum[SCAN_G];
__device__ uint2 g_perm[E];                // (edge_id, src), sorted by dst
__device__ int   g_dstp[E];                // dst, sorted (parallel to g_perm)
// W1/W2 split bf16 hi/lo, fragment-major for m16n8k16 B-operand
__device__ uint32_t g_Bh[2][8192];
__device__ uint32_t g_Bl[2][8192];

// ---------------------------------------------------------------------------
// init: seed g_aggr = x, zero cnt + stats
// ---------------------------------------------------------------------------
__global__ void init_kernel(const float* __restrict__ x) {
    int i = blockIdx.x * blockDim.x + threadIdx.x;
    size_t total = (size_t)Nn * 32;
    if ((size_t)i < total)
        reinterpret_cast<float4*>(g_aggr)[i] = __ldg(reinterpret_cast<const float4*>(x) + i);
    if (i < Nn) g_cnt[i] = 0;
    if (i < 2 * D) g_stats[i] = 0.f;
}

// ---------------------------------------------------------------------------
// CSR build: histogram -> 3-step scan -> scatter
// ---------------------------------------------------------------------------
__global__ void hist_kernel(const int* __restrict__ ei) {
    int e = blockIdx.x * blockDim.x + threadIdx.x;
    if (e < E) atomicAdd(&g_cnt[__ldg(ei + E + e)], 1);
}

__global__ void scan1_kernel() {
    __shared__ int sm[SCAN_B];
    int i = blockIdx.x * SCAN_B + threadIdx.x;
    int v = (i < Nn) ? g_cnt[i] : 0;
    sm[threadIdx.x] = v;
    __syncthreads();
#pragma unroll
    for (int off = 1; off < SCAN_B; off <<= 1) {
        int t = (threadIdx.x >= off) ? sm[threadIdx.x - off] : 0;
        __syncthreads();
        sm[threadIdx.x] += t;
        __syncthreads();
    }
    if (i < Nn) g_start[i] = sm[threadIdx.x] - v;
    if (threadIdx.x == SCAN_B - 1) g_bsum[blockIdx.x] = sm[SCAN_B - 1];
}

__global__ void scan2_kernel() {
    if (threadIdx.x == 0) {
        int s = 0;
        for (int b = 0; b < SCAN_G; b++) { int t = g_bsum[b]; g_bsum[b] = s; s += t; }
    }
}

__global__ void scan3_kernel() {
    int i = blockIdx.x * SCAN_B + threadIdx.x;
    if (i < Nn) {
        int s = g_start[i] + g_bsum[blockIdx.x];
        g_start[i] = s;
        g_cur[i]   = s;
    }
}

__global__ void scatter_kernel(const int* __restrict__ ei) {
    int e = blockIdx.x * blockDim.x + threadIdx.x;
    if (e < E) {
        int src = __ldg(ei + e);
        int dst = __ldg(ei + E + e);
        int pos = atomicAdd(&g_cur[dst], 1);
        g_perm[pos] = make_uint2((unsigned)e, (unsigned)src);
        g_dstp[pos] = dst;
    }
}

// ---------------------------------------------------------------------------
// Balanced segment-reduce aggregate: one warp per 32 sorted edges.
// Interior segments -> plain RMW on pre-seeded g_aggr; boundary -> red.add.
// ---------------------------------------------------------------------------
__device__ __forceinline__ void seg_flush(int dst, float4 acc, int base, int lane) {
    int st = __ldg(&g_start[dst]);
    int en = st + __ldg(&g_cnt[dst]);
    float* p = g_aggr + (size_t)dst * D + lane * 4;
    if (st >= base && en <= base + 32) {
        float4 o = *reinterpret_cast<float4*>(p);
        o.x += acc.x; o.y += acc.y; o.z += acc.z; o.w += acc.w;
        *reinterpret_cast<float4*>(p) = o;
    } else {
        asm volatile("red.global.add.v2.f32 [%0], {%1, %2};" :: "l"(p),     "f"(acc.x), "f"(acc.y) : "memory");
        asm volatile("red.global.add.v2.f32 [%0], {%1, %2};" :: "l"(p + 2), "f"(acc.z), "f"(acc.w) : "memory");
    }
}

__global__ __launch_bounds__(256)
void aggregate_kernel(const float* __restrict__ x, const float* __restrict__ ea) {
    int warp = (int)(((size_t)blockIdx.x * blockDim.x + threadIdx.x) >> 5);
    int lane = threadIdx.x & 31;
    int base = warp * 32;
    if (base >= E) return;
    const float4* x4  = reinterpret_cast<const float4*>(x);
    const float4* ea4 = reinterpret_cast<const float4*>(ea);
    uint2 p = __ldg(g_perm + base + lane);
    int   d = __ldg(g_dstp + base + lane);
    float4 acc = make_float4(0.f, 0.f, 0.f, 0.f);
    int cur = __shfl_sync(0xffffffffu, d, 0);
#pragma unroll
    for (int g = 0; g < 32; g += 8) {
        float4 xs[8], es[8];
#pragma unroll
        for (int u = 0; u < 8; u++) {
            uint32_t e = __shfl_sync(0xffffffffu, p.x, g + u);
            uint32_t s = __shfl_sync(0xffffffffu, p.y, g + u);
            xs[u] = __ldg(x4 + (size_t)s * 32 + lane);
            es[u] = __ldg(ea4 + (size_t)e * 32 + lane);
        }
#pragma unroll
        for (int u = 0; u < 8; u++) {
            int dj = __shfl_sync(0xffffffffu, d, g + u);
            if (dj != cur) {                 // uniform across warp
                seg_flush(cur, acc, base, lane);
                acc = make_float4(0.f, 0.f, 0.f, 0.f);
                cur = dj;
            }
            acc.x += fmaxf(xs[u].x + es[u].x, 0.f);
            acc.y += fmaxf(xs[u].y + es[u].y, 0.f);
            acc.z += fmaxf(xs[u].z + es[u].z, 0.f);
            acc.w += fmaxf(xs[u].w + es[u].w, 0.f);
        }
    }
    seg_flush(cur, acc, base, lane);
}

// ---------------------------------------------------------------------------
// prep: W -> bf16 hi/lo fragment-major for m16n8k16 B-operand.
// ---------------------------------------------------------------------------
__global__ void prep_kernel(const float* __restrict__ W1, const float* __restrict__ W2) {
    const float* W = blockIdx.x ? W2 : W1;
    uint32_t* bh = g_Bh[blockIdx.x];
    uint32_t* bl = g_Bl[blockIdx.x];
    for (int i = threadIdx.x; i < 64 * 128; i += blockDim.x) {
        int k2 = i >> 7, c = i & 127, k = k2 * 2;
        float w0 = __ldg(W + (size_t)k * D + c);
        float w1 = __ldg(W + (size_t)(k + 1) * D + c);
        __nv_bfloat16 h0 = __float2bfloat16(w0);
        __nv_bfloat16 h1 = __float2bfloat16(w1);
        __nv_bfloat16 l0 = __float2bfloat16(w0 - __bfloat162float(h0));
        __nv_bfloat16 l1 = __float2bfloat16(w1 - __bfloat162float(h1));
        int kstep = k2 >> 3;
        int n16   = c >> 4;
        int lane  = (c & 7) * 4 + (k2 & 3);
        int slot  = 2 * ((c >> 3) & 1) + ((k2 >> 2) & 1);
        int idx   = ((kstep * 8 + n16) * 32 + lane) * 4 + slot;
        bh[idx] = (uint32_t)__bfloat16_as_ushort(h0) | ((uint32_t)__bfloat16_as_ushort(h1) << 16);
        bl[idx] = (uint32_t)__bfloat16_as_ushort(l0) | ((uint32_t)__bfloat16_as_ushort(l1) << 16);
    }
}

// ---------------------------------------------------------------------------
// Fused 2-layer MLP: 128x128 tile, 512 threads (4x4 warp grid).
// GEMM1 -> relu+b1 -> T written back into A smem (fragment-major, hi/lo) ->
// GEMM2 -> out = x + T@W2 + b2 (+ BN column stats). No g_t round trip.
// ---------------------------------------------------------------------------
#define MMA_BF16(d, av, b0, b1) \
    asm volatile("mma.sync.aligned.m16n8k16.row.col.f32.bf16.bf16.f32 " \
                 "{%0,%1,%2,%3},{%4,%5,%6,%7},{%8,%9},{%0,%1,%2,%3};" \
                 : "+f"((d)[0]), "+f"((d)[1]), "+f"((d)[2]), "+f"((d)[3]) \
                 : "r"((av).x), "r"((av).y), "r"((av).z), "r"((av).w), \
                   "r"(b0), "r"(b1))

__global__ __launch_bounds__(512, 1)
void mlp_fused(const float* __restrict__ x, const float* __restrict__ b1,
               const float* __restrict__ b2, float* __restrict__ out) {
    extern __shared__ __align__(16) unsigned char smem[];
    uint32_t* Ah  = reinterpret_cast<uint32_t*>(smem);   // [8192] (A, later T)
    uint32_t* Al  = Ah + 8192;
    uint32_t* B1h = Al + 8192;
    uint32_t* B1l = B1h + 8192;
    uint32_t* B2h = B1l + 8192;
    uint32_t* B2l = B2h + 8192;
    float* cs = reinterpret_cast<float*>(B2l + 8192);    // [128]
    float* cq = cs + 128;
    const int tid = threadIdx.x, wid = tid >> 5, lane = tid & 31;
    const int r0 = blockIdx.x * 128;

    // B tiles (linear copy of pre-packed fragments)
    {
        const uint4* s1h = reinterpret_cast<const uint4*>(g_Bh[0]);
        const uint4* s1l = reinterpret_cast<const uint4*>(g_Bl[0]);
        const uint4* s2h = reinterpret_cast<const uint4*>(g_Bh[1]);
        const uint4* s2l = reinterpret_cast<const uint4*>(g_Bl[1]);
        uint4* d1h = reinterpret_cast<uint4*>(B1h);
        uint4* d1l = reinterpret_cast<uint4*>(B1l);
        uint4* d2h = reinterpret_cast<uint4*>(B2h);
        uint4* d2l = reinterpret_cast<uint4*>(B2l);
#pragma unroll
        for (int i = tid; i < 2048; i += 512) {
            d1h[i] = __ldg(s1h + i); d1l[i] = __ldg(s1l + i);
            d2h[i] = __ldg(s2h + i); d2l[i] = __ldg(s2l + i);
        }
    }

    // A = g_aggr (= x + aggr): load, hi/lo split, fragment-major pack
    for (int i = tid; i < 4096; i += 512) {
        int r = i >> 5, q = i & 31;
        int gr = r0 + r;
        float4 a = make_float4(0.f, 0.f, 0.f, 0.f);
        if (gr < Nn)
            a = *(reinterpret_cast<const float4*>(g_aggr) + (size_t)gr * 32 + q);
        __nv_bfloat16 h0 = __float2bfloat16(a.x), h1 = __float2bfloat16(a.y);
        __nv_bfloat16 h2 = __float2bfloat16(a.z), h3 = __float2bfloat16(a.w);
        __nv_bfloat16 l0 = __float2bfloat16(a.x - __bfloat162float(h0));
        __nv_bfloat16 l1 = __float2bfloat16(a.y - __bfloat162float(h1));
        __nv_bfloat16 l2 = __float2bfloat16(a.z - __bfloat162float(h2));
        __nv_bfloat16 l3 = __float2bfloat16(a.w - __bfloat162float(h3));
        uint32_t hp0 = (uint32_t)__bfloat16_as_ushort(h0) | ((uint32_t)__bfloat16_as_ushort(h1) << 16);
        uint32_t hp1 = (uint32_t)__bfloat16_as_ushort(h2) | ((uint32_t)__bfloat16_as_ushort(h3) << 16);
        uint32_t lp0 = (uint32_t)__bfloat16_as_ushort(l0) | ((uint32_t)__bfloat16_as_ushort(l1) << 16);
        uint32_t lp1 = (uint32_t)__bfloat16_as_ushort(l2) | ((uint32_t)__bfloat16_as_ushort(l3) << 16);
        int kstep = q >> 2;
        int m16   = r >> 4;
        int l     = (r & 7) * 4 + (q & 1) * 2;
        int s     = ((r >> 3) & 1) + 2 * ((q >> 1) & 1);
        int base  = (kstep * 8 + m16) * 32;
        int i0 = (base + ((l)     ^ kstep)) * 4 + s;
        int i1 = (base + ((l + 1) ^ kstep)) * 4 + s;
        Ah[i0] = hp0; Ah[i1] = hp1;
        Al[i0] = lp0; Al[i1] = lp1;
    }
    if (tid < 128) { cs[tid] = 0.f; cq[tid] = 0.f; }
    __syncthreads();

    const int wm = wid & 3, wn = wid >> 2;
    const int tg = lane >> 2, tc = lane & 3;
    float acc[2][2][2][4];

    // ---------------- GEMM1 ----------------
#pragma unroll
    for (int im = 0; im < 2; im++)
#pragma unroll
        for (int in = 0; in < 2; in++)
#pragma unroll
            for (int j = 0; j < 2; j++)
#pragma unroll
                for (int v = 0; v < 4; v++) acc[im][in][j][v] = 0.f;

#pragma unroll
    for (int ks = 0; ks < 8; ks++) {
        uint4 ahv[2], alv[2], bhv[2], blv[2];
#pragma unroll
        for (int im = 0; im < 2; im++) {
            int idx = ((ks * 8 + wm * 2 + im) * 32 + (lane ^ ks)) * 4;
            ahv[im] = *reinterpret_cast<const uint4*>(Ah + idx);
            alv[im] = *reinterpret_cast<const uint4*>(Al + idx);
        }
#pragma unroll
        for (int in = 0; in < 2; in++) {
            int idx = ((ks * 8 + wn * 2 + in) * 32 + lane) * 4;
            bhv[in] = *reinterpret_cast<const uint4*>(B1h + idx);
            blv[in] = *reinterpret_cast<const uint4*>(B1l + idx);
        }
#pragma unroll
        for (int im = 0; im < 2; im++)
#pragma unroll
            for (int in = 0; in < 2; in++)
#pragma unroll
                for (int j = 0; j < 2; j++) {
                    uint32_t b0h = j ? bhv[in].z : bhv[in].x;
                    uint32_t b1h_ = j ? bhv[in].w : bhv[in].y;
                    uint32_t b0l = j ? blv[in].z : blv[in].x;
                    uint32_t b1l_ = j ? blv[in].w : blv[in].y;
                    MMA_BF16(acc[im][in][j], ahv[im], b0h, b1h_);
                    MMA_BF16(acc[im][in][j], ahv[im], b0l, b1l_);
                    MMA_BF16(acc[im][in][j], alv[im], b0h, b1h_);
                }
    }
    __syncthreads();   // everyone done reading A tiles

    // ---------------- T = relu(acc + b1) -> back into Ah/Al ----------------
#pragma unroll
    for (int im = 0; im < 2; im++)
#pragma unroll
        for (int rh = 0; rh < 2; rh++) {
            int r = (wm * 2 + im) * 16 + rh * 8 + tg;
#pragma unroll
            for (int in = 0; in < 2; in++)
#pragma unroll
                for (int j = 0; j < 2; j++) {
                    int c = wn * 32 + in * 16 + j * 8 + tc * 2;
                    float2 bb = __ldg(reinterpret_cast<const float2*>(b1 + c));
                    float v0 = fmaxf(acc[im][in][j][rh * 2]     + bb.x, 0.f);
                    float v1 = fmaxf(acc[im][in][j][rh * 2 + 1] + bb.y, 0.f);
                    __nv_bfloat16 h0 = __float2bfloat16(v0), h1 = __float2bfloat16(v1);
                    __nv_bfloat16 l0 = __float2bfloat16(v0 - __bfloat162float(h0));
                    __nv_bfloat16 l1 = __float2bfloat16(v1 - __bfloat162float(h1));
                    // fragment index (same map as prologue pack)
                    int kstep = c >> 4;               // = wn*2+in
                    int m16   = r >> 4;               // = wm*2+im
                    int l     = (r & 7) * 4 + (((c >> 2) & 1) * 2) + ((c >> 1) & 1);
                    int s     = ((r >> 3) & 1) + 2 * ((c >> 3) & 1);
                    int idx   = ((kstep * 8 + m16) * 32 + (l ^ kstep)) * 4 + s;
                    Ah[idx] = (uint32_t)__bfloat16_as_ushort(h0) | ((uint32_t)__bfloat16_as_ushort(h1) << 16);
                    Al[idx] = (uint32_t)__bfloat16_as_ushort(l0) | ((uint32_t)__bfloat16_as_ushort(l1) << 16);
                }
        }
    __syncthreads();

    // ---------------- GEMM2 ----------------
#pragma unroll
    for (int im = 0; im < 2; im++)
#pragma unroll
        for (int in = 0; in < 2; in++)
#pragma unroll
            for (int j = 0; j < 2; j++)
#pragma unroll
                for (int v = 0; v < 4; v++) acc[im][in][j][v] = 0.f;

#pragma unroll
    for (int ks = 0; ks < 8; ks++) {
        uint4 ahv[2], alv[2], bhv[2], blv[2];
#pragma unroll
        for (int im = 0; im < 2; im++) {
            int idx = ((ks * 8 + wm * 2 + im) * 32 + (lane ^ ks)) * 4;
            ahv[im] = *reinterpret_cast<const uint4*>(Ah + idx);
            alv[im] = *reinterpret_cast<const uint4*>(Al + idx);
        }
#pragma unroll
        for (int in = 0; in < 2; in++) {
            int idx = ((ks * 8 + wn * 2 + in) * 32 + lane) * 4;
            bhv[in] = *reinterpret_cast<const uint4*>(B2h + idx);
            blv[in] = *reinterpret_cast<const uint4*>(B2l + idx);
        }
#pragma unroll
        for (int im = 0; im < 2; im++)
#pragma unroll
            for (int in = 0; in < 2; in++)
#pragma unroll
                for (int j = 0; j < 2; j++) {
                    uint32_t b0h = j ? bhv[in].z : bhv[in].x;
                    uint32_t b1h_ = j ? bhv[in].w : bhv[in].y;
                    uint32_t b0l = j ? blv[in].z : blv[in].x;
                    uint32_t b1l_ = j ? blv[in].w : blv[in].y;
                    MMA_BF16(acc[im][in][j], ahv[im], b0h, b1h_);
                    MMA_BF16(acc[im][in][j], ahv[im], b0l, b1l_);
                    MMA_BF16(acc[im][in][j], alv[im], b0h, b1h_);
                }
    }

    // ---------------- Epilogue: out = x + acc + b2, BN stats ----------------
    float2 bv[2][2];
#pragma unroll
    for (int in = 0; in < 2; in++)
#pragma unroll
        for (int j = 0; j < 2; j++)
            bv[in][j] = __ldg(reinterpret_cast<const float2*>(b2 + wn * 32 + in * 16 + j * 8 + tc * 2));

    float s8[8], q8[8];
#pragma unroll
    for (int u = 0; u < 8; u++) { s8[u] = 0.f; q8[u] = 0.f; }
#pragma unroll
    for (int im = 0; im < 2; im++)
#pragma unroll
        for (int rh = 0; rh < 2; rh++) {
            int gr = r0 + (wm * 2 + im) * 16 + rh * 8 + tg;
            if (gr < Nn) {
                const float* xr = x + (size_t)gr * D;
                float* op = out + (size_t)gr * D;
#pragma unroll
                for (int in = 0; in < 2; in++)
#pragma unroll
                    for (int j = 0; j < 2; j++) {
                        int col = wn * 32 + in * 16 + j * 8 + tc * 2;
                        float2 xv = __ldg(reinterpret_cast<const float2*>(xr + col));
                        float v0 = acc[im][in][j][rh * 2]     + bv[in][j].x + xv.x;
                        float v1 = acc[im][in][j][rh * 2 + 1] + bv[in][j].y + xv.y;
                        int ci = in * 4 + j * 2;
                        s8[ci] += v0;     q8[ci] += v0 * v0;
                        s8[ci + 1] += v1; q8[ci + 1] += v1 * v1;
                        *reinterpret_cast<float2*>(op + col) = make_float2(v0, v1);
                    }
            }
        }
#pragma unroll
    for (int in = 0; in < 2; in++)
#pragma unroll
        for (int j = 0; j < 2; j++)
#pragma unroll
            for (int h = 0; h < 2; h++) {
                int col = wn * 32 + in * 16 + j * 8 + tc * 2 + h;
                int ci = in * 4 + j * 2 + h;
                atomicAdd(&cs[col], s8[ci]);
                atomicAdd(&cq[col], q8[ci]);
            }
    __syncthreads();
    if (tid < 128) {
        atomicAdd(&g_stats[tid],     cs[tid]);
        atomicAdd(&g_stats[D + tid], cq[tid]);
    }
}

// ---------------------------------------------------------------------------
// BN: compute scale/shift from stats (per block, cheap) then apply in place.
// ---------------------------------------------------------------------------
__global__ void bn_kernel(float* __restrict__ out,
                          const float* __restrict__ bn_w,
                          const float* __restrict__ bn_b) {
    __shared__ float sc_s[D], sh_s[D];
    int tid = threadIdx.x;
    if (tid < D) {
        float inv_n = 1.f / (float)Nn;
        float mean  = g_stats[tid] * inv_n;
        float var   = g_stats[D + tid] * inv_n - mean * mean;
        float rstd  = rsqrtf(var + 1e-5f);
        float sc    = rstd * __ldg(bn_w + tid);
        sc_s[tid] = sc;
        sh_s[tid] = __ldg(bn_b + tid) - mean * sc;
    }
    __syncthreads();
    size_t stride = (size_t)gridDim.x * blockDim.x;
    size_t total  = (size_t)Nn * 32;
    for (size_t v = (size_t)blockIdx.x * blockDim.x + tid; v < total; v += stride) {
        int q = (int)(v & 31);
        float4 h = reinterpret_cast<float4*>(out)[v];
        float4 sc = *reinterpret_cast<const float4*>(sc_s + q * 4);
        float4 sh = *reinterpret_cast<const float4*>(sh_s + q * 4);
        h.x = h.x * sc.x + sh.x;
        h.y = h.y * sc.y + sh.y;
        h.z = h.z * sc.z + sh.z;
        h.w = h.w * sc.w + sh.w;
        reinterpret_cast<float4*>(out)[v] = h;
    }
}

// ---------------------------------------------------------------------------
extern "C" void kernel_launch(void* const* d_in, const int* in_sizes, int n_in,
                              void* d_out, int out_size) {
    const float* x   = (const float*)d_in[0];
    const int*   ei  = (const int*)d_in[1];
    const float* ea  = (const float*)d_in[2];
    const float* W1  = (const float*)d_in[3];
    const float* b1  = (const float*)d_in[4];
    const float* W2  = (const float*)d_in[5];
    const float* b2  = (const float*)d_in[6];
    const float* bnw = (const float*)d_in[7];
    const float* bnb = (const float*)d_in[8];
    float* out = (float*)d_out;

    init_kernel<<<(Nn * 32 + 255) / 256, 256>>>(x);
    prep_kernel<<<2, 256>>>(W1, W2);
    hist_kernel<<<(E + 255) / 256, 256>>>(ei);
    scan1_kernel<<<SCAN_G, SCAN_B>>>();
    scan2_kernel<<<1, 32>>>();
    scan3_kernel<<<SCAN_G, SCAN_B>>>();
    scatter_kernel<<<(E + 255) / 256, 256>>>(ei);
    aggregate_kernel<<<(E / 32 + 7) / 8, 256>>>(x, ea);   // warp per 32 edges

    int smem_bytes = 6 * 8192 * 4 + 256 * 4;   // 197,632 B
    cudaFuncSetAttribute(mlp_fused, cudaFuncAttributeMaxDynamicSharedMemorySize, smem_bytes);
    mlp_fused<<<(Nn + 127) / 128, 512, smem_bytes>>>(x, b1, b2, out);

    bn_kernel<<<1024, 256>>>(out, bnw, bnb);
}